// round 3
// baseline (speedup 1.0000x reference)
#include <cuda_runtime.h>
#include <cstdint>

#define RANK  200
#define NNZ   500000
#define N_ENT 200000
#define N_REL 500
#define RV4   (RANK / 4)   // 50 float4 per row

// Scratch (__device__ globals; every array is either fully overwritten each
// invocation or explicitly reset, so graph replays are deterministic).
__device__ float g_deriv[NNZ];     // 2 * (kruskal - val) per nnz
__device__ int   g_win_a[N_ENT];   // winner key: n+1 (subj) or n+1+NNZ (obj); 0 = none (self-reset in pass_b)
__device__ int   g_win_b[N_REL];   // winner key: n+1; 0 = none (self-reset in pass_b)
__device__ int   g_hist[N_REL];    // relation histogram (zeroed each invocation)
__device__ int   g_off[N_REL];     // bucket offsets (rebuilt each invocation)
__device__ int4  g_sorted[NNZ];    // (s, r, o, n) sorted by relation (fully rewritten)

// ---------------------------------------------------------------------------
// Sort stage 0: zero the histogram.
// ---------------------------------------------------------------------------
__global__ void zero_hist_kernel() {
    int i = threadIdx.x;
    if (i < N_REL) g_hist[i] = 0;
}

// ---------------------------------------------------------------------------
// Sort stage 1: per-block smem histogram of relations, merged to global.
// ---------------------------------------------------------------------------
__global__ void __launch_bounds__(256) hist_kernel(const int* __restrict__ coo) {
    __shared__ int sh[N_REL];
    for (int i = threadIdx.x; i < N_REL; i += blockDim.x) sh[i] = 0;
    __syncthreads();
    int stride = gridDim.x * blockDim.x;
    for (int n = blockIdx.x * blockDim.x + threadIdx.x; n < NNZ; n += stride)
        atomicAdd(&sh[coo[3 * n + 1]], 1);
    __syncthreads();
    for (int i = threadIdx.x; i < N_REL; i += blockDim.x)
        if (sh[i]) atomicAdd(&g_hist[i], sh[i]);
}

// ---------------------------------------------------------------------------
// Sort stage 2: exclusive scan of 500 bucket counts (single block).
// ---------------------------------------------------------------------------
__global__ void scan_kernel() {
    __shared__ int sh[512];
    int i = threadIdx.x;
    sh[i] = (i < N_REL) ? g_hist[i] : 0;
    __syncthreads();
    for (int d = 1; d < 512; d <<= 1) {
        int v = (i >= d) ? sh[i - d] : 0;
        __syncthreads();
        sh[i] += v;
        __syncthreads();
    }
    if (i < N_REL) g_off[i] = (i == 0) ? 0 : sh[i - 1];
}

// ---------------------------------------------------------------------------
// Sort stage 3: scatter packed (s,r,o,n) into relation buckets.
// ---------------------------------------------------------------------------
__global__ void __launch_bounds__(256) scatter_kernel(const int* __restrict__ coo) {
    int n = blockIdx.x * blockDim.x + threadIdx.x;
    if (n >= NNZ) return;
    int s = coo[3 * n + 0];
    int r = coo[3 * n + 1];
    int o = coo[3 * n + 2];
    int pos = atomicAdd(&g_off[r], 1);
    g_sorted[pos] = make_int4(s, r, o, n);
}

// ---------------------------------------------------------------------------
// Pass A: one warp per sorted nnz. Relation-sorted order means consecutive
// warps share the same b row -> b gathers hit L1 and drop out of LTS traffic.
// Rank-200 dot via warp reduction; winners raced with atomicMax using the
// ORIGINAL nnz index n, reproducing XLA scatter-overwrite semantics
// (obj class beats subj class; within a class, higher n wins).
// ---------------------------------------------------------------------------
__global__ void __launch_bounds__(256) pass_a_kernel(
    const float* __restrict__ vals,
    const float* __restrict__ a,
    const float* __restrict__ b,
    float*       __restrict__ loss)
{
    int warp = (blockIdx.x * blockDim.x + threadIdx.x) >> 5;
    int lane = threadIdx.x & 31;
    if (warp >= NNZ) return;

    int4 t = g_sorted[warp];   // same address across the warp -> broadcast
    int s = t.x, r = t.y, o = t.z, n = t.w;

    const float4* a0 = (const float4*)(a + (size_t)s * RANK);
    const float4* b1 = (const float4*)(b + (size_t)r * RANK);
    const float4* a2 = (const float4*)(a + (size_t)o * RANK);

    float sum = 0.0f;
    #pragma unroll
    for (int it = 0; it < 2; it++) {
        int j = lane + it * 32;
        if (j < RV4) {
            float4 x = __ldg(a0 + j);
            float4 y = __ldg(b1 + j);
            float4 z = __ldg(a2 + j);
            sum += x.x * y.x * z.x;
            sum += x.y * y.y * z.y;
            sum += x.z * y.z * z.z;
            sum += x.w * y.w * z.w;
        }
    }
    #pragma unroll
    for (int off = 16; off; off >>= 1)
        sum += __shfl_down_sync(0xffffffffu, sum, off);

    if (lane == 0) {
        float diff = sum - __ldg(vals + n);
        __stcs(loss + n, diff * diff);          // streaming: never re-read
        g_deriv[n] = 2.0f * diff;
        atomicMax(&g_win_a[s], n + 1);          // subj class
        atomicMax(&g_win_a[o], n + 1 + NNZ);    // obj class (beats subj)
        atomicMax(&g_win_b[r], n + 1);
    }
}

// ---------------------------------------------------------------------------
// Pass B (fused): warps [0, N_ENT) -> grad_a rows, warps [N_ENT, N_ENT+N_REL)
// -> grad_b rows. Loser rows get zeros (doubles as output init). Winner rows
// re-gather the two needed embedding rows and write d * x * y with streaming
// stores. Each warp resets its winner slot to 0 for the next invocation.
// ---------------------------------------------------------------------------
__global__ void __launch_bounds__(256) pass_b_kernel(
    const int*   __restrict__ coo,
    const float* __restrict__ a,
    const float* __restrict__ b,
    float*       __restrict__ grad_a,
    float*       __restrict__ grad_b)
{
    int warp = (blockIdx.x * blockDim.x + threadIdx.x) >> 5;
    int lane = threadIdx.x & 31;
    if (warp >= N_ENT + N_REL) return;

    float4* out;
    const float4* x;
    const float4* y;
    float d = 0.0f;
    bool have = false;

    if (warp < N_ENT) {
        out = (float4*)(grad_a + (size_t)warp * RANK);
        int k = g_win_a[warp];
        if (k > 0) {
            if (lane == 0) g_win_a[warp] = 0;        // self-reset
            bool is_obj = (k > NNZ);
            int  n      = is_obj ? (k - 1 - NNZ) : (k - 1);
            int s = coo[3 * n + 0];
            int r = coo[3 * n + 1];
            int o = coo[3 * n + 2];
            d = g_deriv[n];
            if (is_obj) {        // g_c = d * a0 * b1
                x = (const float4*)(a + (size_t)s * RANK);
                y = (const float4*)(b + (size_t)r * RANK);
            } else {             // g_a = d * b1 * a2
                x = (const float4*)(b + (size_t)r * RANK);
                y = (const float4*)(a + (size_t)o * RANK);
            }
            have = true;
        }
    } else {
        int row = warp - N_ENT;
        out = (float4*)(grad_b + (size_t)row * RANK);
        int k = g_win_b[row];
        if (k > 0) {
            if (lane == 0) g_win_b[row] = 0;         // self-reset
            int n = k - 1;
            int s = coo[3 * n + 0];
            int o = coo[3 * n + 2];
            d = g_deriv[n];
            x = (const float4*)(a + (size_t)s * RANK);   // g_b = d * a0 * a2
            y = (const float4*)(a + (size_t)o * RANK);
            have = true;
        }
    }

    if (!have) {
        float4 z = make_float4(0.f, 0.f, 0.f, 0.f);
        #pragma unroll
        for (int it = 0; it < 2; it++) {
            int j = lane + it * 32;
            if (j < RV4) __stcs(out + j, z);
        }
        return;
    }

    #pragma unroll
    for (int it = 0; it < 2; it++) {
        int j = lane + it * 32;
        if (j < RV4) {
            float4 u = __ldg(x + j);
            float4 v = __ldg(y + j);
            float4 w = make_float4(d * u.x * v.x, d * u.y * v.y,
                                   d * u.z * v.z, d * u.w * v.w);
            __stcs(out + j, w);
        }
    }
}

// ---------------------------------------------------------------------------
// Launch. Inputs (metadata order): coo_ns int32 [NNZ,3], vals_ns f32 [NNZ],
// a f32 [N_ENT,RANK], b f32 [N_REL,RANK].
// Output: loss[NNZ] | grad_a[N_ENT*RANK] | grad_b[N_REL*RANK]  (f32).
// ---------------------------------------------------------------------------
extern "C" void kernel_launch(void* const* d_in, const int* in_sizes, int n_in,
                              void* d_out, int out_size)
{
    const int*   coo  = (const int*)d_in[0];
    const float* vals = (const float*)d_in[1];
    const float* a    = (const float*)d_in[2];
    const float* b    = (const float*)d_in[3];

    float* out    = (float*)d_out;
    float* loss   = out;
    float* grad_a = out + NNZ;
    float* grad_b = out + NNZ + (size_t)N_ENT * RANK;

    zero_hist_kernel<<<1, 512>>>();
    hist_kernel<<<296, 256>>>(coo);
    scan_kernel<<<1, 512>>>();
    scatter_kernel<<<(NNZ + 255) / 256, 256>>>(coo);

    {   // one warp per sorted nnz
        long long threads = (long long)NNZ * 32;
        int blocks = (int)((threads + 255) / 256);
        pass_a_kernel<<<blocks, 256>>>(vals, a, b, loss);
    }
    {   // one warp per output row (entity rows then relation rows)
        long long threads = (long long)(N_ENT + N_REL) * 32;
        int blocks = (int)((threads + 255) / 256);
        pass_b_kernel<<<blocks, 256>>>(coo, a, b, grad_a, grad_b);
    }
}

// round 4
// speedup vs baseline: 2.4346x; 2.4346x over previous
#include <cuda_runtime.h>
#include <cstdint>

#define RANK  200
#define NNZ   500000
#define N_ENT 200000
#define N_REL 500
#define RV4   (RANK / 4)   // 50 float4 per row

// Scratch (__device__ globals: zero-initialized at module load; pass_b
// self-resets winner slots to 0 after consuming them so every invocation —
// correctness run and each graph replay — starts identically).
__device__ float g_deriv[NNZ];     // 2 * (kruskal - val) per nnz
__device__ int   g_win_a[N_ENT];   // winner key: n+1 (subj) or n+1+NNZ (obj); 0 = none
__device__ int   g_win_b[N_REL];   // winner key: n+1; 0 = none

// L2-only float4 load (bypass L1): for `a` gathers, which have no L1 reuse
// and would otherwise evict the highly-reused `b` rows from L1.
__device__ __forceinline__ float4 ldcg4(const float4* p) { return __ldcg(p); }
// L1-cached float4 load: for `b` gathers (~7x temporal reuse per SM).
__device__ __forceinline__ float4 ldg4(const float4* p)  { return __ldg(p); }

// ---------------------------------------------------------------------------
// Pass A: one warp per nnz. Gather a0/b1/a2, rank-200 dot via warp reduction,
// emit loss + deriv, and race the scatter-overwrite winners with atomicMax.
// Key encoding reproduces XLA sequential-scatter semantics:
//   grad_a: obj writes (.set applied second) beat subj writes -> key n+1+NNZ
//   vs n+1; within a class, higher nnz index wins (last update wins).
// ---------------------------------------------------------------------------
__global__ void __launch_bounds__(256) pass_a_kernel(
    const int*   __restrict__ coo,
    const float* __restrict__ vals,
    const float* __restrict__ a,
    const float* __restrict__ b,
    float*       __restrict__ loss)
{
    int warp = (blockIdx.x * blockDim.x + threadIdx.x) >> 5;
    int lane = threadIdx.x & 31;
    if (warp >= NNZ) return;

    int s = coo[3 * warp + 0];
    int r = coo[3 * warp + 1];
    int o = coo[3 * warp + 2];

    const float4* a0 = (const float4*)(a + (size_t)s * RANK);
    const float4* b1 = (const float4*)(b + (size_t)r * RANK);
    const float4* a2 = (const float4*)(a + (size_t)o * RANK);

    float sum = 0.0f;
    #pragma unroll
    for (int it = 0; it < 2; it++) {
        int j = lane + it * 32;
        if (j < RV4) {
            float4 x = ldcg4(a0 + j);   // a: L2-only
            float4 z = ldcg4(a2 + j);   // a: L2-only
            float4 y = ldg4 (b1 + j);   // b: L1-cached
            sum += x.x * y.x * z.x;
            sum += x.y * y.y * z.y;
            sum += x.z * y.z * z.z;
            sum += x.w * y.w * z.w;
        }
    }
    #pragma unroll
    for (int off = 16; off; off >>= 1)
        sum += __shfl_down_sync(0xffffffffu, sum, off);

    if (lane == 0) {
        float diff = sum - __ldg(vals + warp);
        __stcs(loss + warp, diff * diff);       // streaming: never re-read
        g_deriv[warp] = 2.0f * diff;
        atomicMax(&g_win_a[s], warp + 1);       // subj class
        atomicMax(&g_win_a[o], warp + 1 + NNZ); // obj class (beats subj)
        atomicMax(&g_win_b[r], warp + 1);
    }
}

// ---------------------------------------------------------------------------
// Pass B (fused): warps [0, N_ENT) -> grad_a rows, warps [N_ENT, N_ENT+N_REL)
// -> grad_b rows. Loser rows get zeros (doubles as output init). Winner rows
// re-gather the two needed embedding rows and write d * x * y with streaming
// stores. Each warp resets its winner slot to 0 for the next invocation.
// ---------------------------------------------------------------------------
__global__ void __launch_bounds__(256) pass_b_kernel(
    const int*   __restrict__ coo,
    const float* __restrict__ a,
    const float* __restrict__ b,
    float*       __restrict__ grad_a,
    float*       __restrict__ grad_b)
{
    int warp = (blockIdx.x * blockDim.x + threadIdx.x) >> 5;
    int lane = threadIdx.x & 31;
    if (warp >= N_ENT + N_REL) return;

    float4* out;
    const float4* x;
    const float4* y;
    float d = 0.0f;
    bool have = false;
    bool x_is_a = false, y_is_a = false;

    if (warp < N_ENT) {
        out = (float4*)(grad_a + (size_t)warp * RANK);
        int k = g_win_a[warp];
        if (k > 0) {
            if (lane == 0) g_win_a[warp] = 0;        // self-reset
            bool is_obj = (k > NNZ);
            int  n      = is_obj ? (k - 1 - NNZ) : (k - 1);
            int s = coo[3 * n + 0];
            int r = coo[3 * n + 1];
            int o = coo[3 * n + 2];
            d = g_deriv[n];
            if (is_obj) {        // g_c = d * a0 * b1
                x = (const float4*)(a + (size_t)s * RANK); x_is_a = true;
                y = (const float4*)(b + (size_t)r * RANK);
            } else {             // g_a = d * b1 * a2
                x = (const float4*)(b + (size_t)r * RANK);
                y = (const float4*)(a + (size_t)o * RANK); y_is_a = true;
            }
            have = true;
        }
    } else {
        int row = warp - N_ENT;
        out = (float4*)(grad_b + (size_t)row * RANK);
        int k = g_win_b[row];
        if (k > 0) {
            if (lane == 0) g_win_b[row] = 0;         // self-reset
            int n = k - 1;
            int s = coo[3 * n + 0];
            int o = coo[3 * n + 2];
            d = g_deriv[n];
            x = (const float4*)(a + (size_t)s * RANK); x_is_a = true;
            y = (const float4*)(a + (size_t)o * RANK); y_is_a = true;
            have = true;
        }
    }

    if (!have) {
        float4 z = make_float4(0.f, 0.f, 0.f, 0.f);
        #pragma unroll
        for (int it = 0; it < 2; it++) {
            int j = lane + it * 32;
            if (j < RV4) __stcs(out + j, z);
        }
        return;
    }

    #pragma unroll
    for (int it = 0; it < 2; it++) {
        int j = lane + it * 32;
        if (j < RV4) {
            float4 u = x_is_a ? ldcg4(x + j) : ldg4(x + j);
            float4 v = y_is_a ? ldcg4(y + j) : ldg4(y + j);
            float4 w = make_float4(d * u.x * v.x, d * u.y * v.y,
                                   d * u.z * v.z, d * u.w * v.w);
            __stcs(out + j, w);
        }
    }
}

// ---------------------------------------------------------------------------
// Launch. Inputs (metadata order): coo_ns int32 [NNZ,3], vals_ns f32 [NNZ],
// a f32 [N_ENT,RANK], b f32 [N_REL,RANK].
// Output: loss[NNZ] | grad_a[N_ENT*RANK] | grad_b[N_REL*RANK]  (f32).
// ---------------------------------------------------------------------------
extern "C" void kernel_launch(void* const* d_in, const int* in_sizes, int n_in,
                              void* d_out, int out_size)
{
    const int*   coo  = (const int*)d_in[0];
    const float* vals = (const float*)d_in[1];
    const float* a    = (const float*)d_in[2];
    const float* b    = (const float*)d_in[3];

    float* out    = (float*)d_out;
    float* loss   = out;
    float* grad_a = out + NNZ;
    float* grad_b = out + NNZ + (size_t)N_ENT * RANK;

    {   // one warp per nnz
        long long threads = (long long)NNZ * 32;
        int blocks = (int)((threads + 255) / 256);
        pass_a_kernel<<<blocks, 256>>>(coo, vals, a, b, loss);
    }
    {   // one warp per output row (entity rows then relation rows)
        long long threads = (long long)(N_ENT + N_REL) * 32;
        int blocks = (int)((threads + 255) / 256);
        pass_b_kernel<<<blocks, 256>>>(coo, a, b, grad_a, grad_b);
    }
}